// round 17
// baseline (speedup 1.0000x reference)
#include <cuda_runtime.h>
#include <cuda_fp16.h>
#include <cstdint>
#include <cstddef>

// FixedGraphAttentionLayer: bs=4, L=20000, D=16, Fin=Fout=128
//   y = x @ W per node (linear rewrite), y stored fp16.
//   e[b,l,d] = s1[adj[b,l,d]] + s2[adj[b,l,0]]  (scores from fp32 accumulators)
// TWO kernels:
//   k1 = HMMA GEMM + fused scores. W converted fp32->fp16 in-block (coalesced)
//        and B fragments produced via ldmatrix.x2.trans (no prep kernel).
//   k2 = dual-node warps (R14-best) with in-block adj dtype detect.
// NOTE: tcgen05 unavailable — harness ptxas targets sm_103 (no 'a' features).

#define LRELU_ALPHA 0.2f
static constexpr int BS = 4;
static constexpr int L  = 20000;
static constexpr int D  = 16;
static constexpr int F  = 128;
static constexpr int NROWS = BS * L;   // 80000

__device__ __align__(16) __half g_yh[(size_t)NROWS * F];   // 20.5 MB
__device__ float g_s1[NROWS];
__device__ float g_s2[NROWS];

__device__ __forceinline__ unsigned smem_u32(const void* p) {
    unsigned a;
    asm("{ .reg .u64 t; cvta.to.shared.u64 t, %1; cvt.u32.u64 %0, t; }" : "=r"(a) : "l"(p));
    return a;
}

// ---------------------------------------------------------------------------
// Kernel 1: y = x @ W via HMMA + fused scores. 256 threads, 64 rows/block.
// Warp w: row-group rw = w&3 (rows rw*16..+15), n-half nh = w>>2
// (n-tiles nh*8..nh*8+7).
// W tile: fp16 row-major [k=128][n=128], 256B rows, 16B chunks swizzled
// chunk' = chunk ^ (k&7). B fragments via ldmatrix.m8n8.x2.trans.b16:
//   lanes 0-15 supply rows kc*16+lane of the 8-col slab -> thread i gets
//   b0 = {W[kc*16+2tg][n], W[kc*16+2tg+1][n]}, b1 = rows +8  (tg=i&3, g=i>>2,
//   n = nt*8+g) — exactly the m16n8k16 B fragment layout.
// ---------------------------------------------------------------------------
__global__ __launch_bounds__(256, 3)
void gemm_scores_kernel(const float* __restrict__ x,
                        const float* __restrict__ W,
                        const float* __restrict__ a)
{
    __shared__ __half2 Xs[64 * 64];    // 16 KB: x tile, then y restage
    __shared__ __half2 Wh[128 * 64];   // 32 KB: fp16 W tile (swizzled chunks)

    const int tid  = threadIdx.x;
    const int lane = tid & 31;
    const int w    = tid >> 5;
    const int rw   = w & 3;            // row group
    const int nh   = w >> 2;           // n half (0..1)
    const int g    = lane >> 2;
    const int tg   = lane & 3;
    const int rowbase = blockIdx.x * 64;

    // convert W fp32 -> fp16 swizzled tile (coalesced loads)
    #pragma unroll
    for (int i = tid; i < 8192; i += 256) {
        const int k = i >> 6, h2 = i & 63;
        float2 v = *(const float2*)(W + k * F + 2 * h2);
        const int c  = h2 >> 2;                    // 16B chunk 0..15
        const int cs = c ^ (k & 7);                // swizzle
        Wh[k * 64 + (cs << 2) + (h2 & 3)] = __floats2half2_rn(v.x, v.y);
    }
    // load x tile (64x128 fp32) -> fp16 swizzled smem
    #pragma unroll
    for (int j = tid; j < 4096; j += 256) {
        const int r = j >> 6, kh2 = j & 63;
        float2 v = *(const float2*)(x + (size_t)(rowbase + r) * F + kh2 * 2);
        Xs[r * 64 + (kh2 ^ ((r & 7) * 4))] = __floats2half2_rn(v.x, v.y);
    }
    __syncthreads();

    // A fragments for this warp's 16 rows, all 8 k-chunks (32 regs)
    unsigned Areg[8][4];
    {
        const int r0 = rw * 16 + g, r1 = r0 + 8;
        const int s  = g * 4;
        #pragma unroll
        for (int kc = 0; kc < 8; kc++) {
            const int kl = kc * 8 + tg, kh = kl + 4;
            Areg[kc][0] = *reinterpret_cast<unsigned*>(&Xs[r0 * 64 + (kl ^ s)]);
            Areg[kc][1] = *reinterpret_cast<unsigned*>(&Xs[r1 * 64 + (kl ^ s)]);
            Areg[kc][2] = *reinterpret_cast<unsigned*>(&Xs[r0 * 64 + (kh ^ s)]);
            Areg[kc][3] = *reinterpret_cast<unsigned*>(&Xs[r1 * 64 + (kh ^ s)]);
        }
    }

    float acc[8][4];
    #pragma unroll
    for (int nt = 0; nt < 8; nt++)
        #pragma unroll
        for (int q = 0; q < 4; q++) acc[nt][q] = 0.f;

    // per-lane ldmatrix row base: row = kc*16 + (lane&15), swizzle uses row&7
    const int  ln16  = lane & 15;
    const unsigned wrow = smem_u32(Wh) + (unsigned)(ln16 * 256);
    const int  swmask = ln16 & 7;

    #pragma unroll
    for (int nt = 0; nt < 8; nt++) {
        const int ntt = nh * 8 + nt;               // chunk index 0..15
        #pragma unroll
        for (int kc = 0; kc < 8; kc++) {
            unsigned b0, b1;
            const unsigned addr = wrow + (unsigned)(kc * 4096 + ((ntt ^ swmask) << 4));
            asm volatile(
                "ldmatrix.sync.aligned.m8n8.x2.trans.shared.b16 {%0,%1}, [%2];"
                : "=r"(b0), "=r"(b1) : "r"(addr));
            asm volatile(
                "mma.sync.aligned.m16n8k16.row.col.f32.f16.f16.f32 "
                "{%0,%1,%2,%3}, {%4,%5,%6,%7}, {%8,%9}, {%0,%1,%2,%3};"
                : "+f"(acc[nt][0]), "+f"(acc[nt][1]), "+f"(acc[nt][2]), "+f"(acc[nt][3])
                : "r"(Areg[kc][0]), "r"(Areg[kc][1]), "r"(Areg[kc][2]), "r"(Areg[kc][3]),
                  "r"(b0), "r"(b1));
        }
    }

    // score partials over this warp's n-half (rows g -> a, g+8 -> b)
    float p1a = 0.f, p1b = 0.f, p2a = 0.f, p2b = 0.f;
    #pragma unroll
    for (int nt = 0; nt < 8; nt++) {
        const float2 a1p = *(const float2*)(a + nh * 64 + nt * 8 + tg * 2);
        const float2 a2p = *(const float2*)(a + F + nh * 64 + nt * 8 + tg * 2);
        p1a += acc[nt][0] * a1p.x + acc[nt][1] * a1p.y;
        p1b += acc[nt][2] * a1p.x + acc[nt][3] * a1p.y;
        p2a += acc[nt][0] * a2p.x + acc[nt][1] * a2p.y;
        p2b += acc[nt][2] * a2p.x + acc[nt][3] * a2p.y;
    }
    #pragma unroll
    for (int o = 1; o <= 2; o <<= 1) {   // reduce over tg quad
        p1a += __shfl_xor_sync(0xffffffffu, p1a, o);
        p1b += __shfl_xor_sync(0xffffffffu, p1b, o);
        p2a += __shfl_xor_sync(0xffffffffu, p2a, o);
        p2b += __shfl_xor_sync(0xffffffffu, p2b, o);
    }

    __syncthreads();   // all Wh ldmatrix + cross-warp Xs A-frag reads complete

    // score partials -> smem (reuse retired Wh region): [nh][row_in_block]
    float* s1p = reinterpret_cast<float*>(Wh);        // 128 floats
    float* s2p = s1p + 128;                           // 128 floats
    if (tg == 0) {
        const int r = rw * 16 + g;
        s1p[nh * 64 + r]     = p1a;
        s1p[nh * 64 + r + 8] = p1b;
        s2p[nh * 64 + r]     = p2a;
        s2p[nh * 64 + r + 8] = p2b;
    }

    // restage y (fp16) into Xs: this warp's n-half columns of its 16 rows
    {
        const int r0 = rw * 16 + g;
        const int s  = g * 4;
        #pragma unroll
        for (int nt = 0; nt < 8; nt++) {
            const int c = nh * 32 + nt * 4 + tg;      // half2 col 0..63
            Xs[r0 * 64 + (c ^ s)]       = __floats2half2_rn(acc[nt][0], acc[nt][1]);
            Xs[(r0 + 8) * 64 + (c ^ s)] = __floats2half2_rn(acc[nt][2], acc[nt][3]);
        }
    }
    __syncthreads();

    // coalesced y stores: 4 threads per row, 16B chunks
    {
        const int r    = tid >> 2;              // 0..63
        const int q    = tid & 3;
        const int s    = (r & 7) * 4;
        const int base = q * 16;                // half2 offset
        __half* dst = g_yh + (size_t)(rowbase + r) * F + base * 2;
        #pragma unroll
        for (int j = 0; j < 4; j++) {
            uint4 v = *reinterpret_cast<uint4*>(&Xs[r * 64 + ((base + j * 4) ^ s)]);
            *reinterpret_cast<uint4*>(dst + j * 8) = v;
        }
    }
    // combine n-half score partials and store
    if (tid < 64) {
        g_s1[rowbase + tid] = s1p[tid] + s1p[64 + tid];
        g_s2[rowbase + tid] = s2p[tid] + s2p[64 + tid];
    }
}

// ---------------------------------------------------------------------------
// Kernel 2 (R14-best): dual-node warps. Warp wg: nodes 2wg (lanes 0-15),
// 2wg+1 (lanes 16-31). Dense softmax, 2 independent row-gathers per iter.
// ---------------------------------------------------------------------------
__global__ __launch_bounds__(256)
void attn_out_kernel(const int* __restrict__ adj32,
                     float* __restrict__ out)
{
    __shared__ int s_is64;
    const int tid  = threadIdx.x;
    const int lane = tid & 31;

    // detect: adj is int64 iff odd 32-bit words are all zero (values < 2^31)
    if (tid < 32) {
        const int bad = (adj32[2 * tid + 1] != 0) | (adj32[2 * tid + 65] != 0);
        const unsigned mm = __ballot_sync(0xffffffffu, bad);
        if (tid == 0) s_is64 = (mm == 0u);
    }
    __syncthreads();
    const int is64 = s_is64;

    const int wg   = (blockIdx.x * blockDim.x + tid) >> 5;
    const int h    = lane >> 4;
    const int li   = lane & 15;
    const int node = wg * 2 + h;
    const size_t nodebase = (size_t)(node / L) * L;

    const size_t ei = (size_t)node * D + li;
    int raw;
    if (is64) {
        long long v = ((const long long*)adj32)[ei];
        raw = (int)v;
    } else {
        raw = adj32[ei];
    }
    raw = raw < 0 ? 0 : (raw >= L ? L - 1 : raw);
    const int idx = raw;
    float e = g_s1[nodebase + idx];

    const int idx0 = __shfl_sync(0xffffffffu, idx, h * 16);
    e += g_s2[nodebase + idx0];
    e = (e >= 0.f) ? e : LRELU_ALPHA * e;

    float m = e;
    #pragma unroll
    for (int o = 8; o > 0; o >>= 1) m = fmaxf(m, __shfl_xor_sync(0xffffffffu, m, o));
    float p = __expf(e - m);
    float s = p;
    #pragma unroll
    for (int o = 8; o > 0; o >>= 1) s += __shfl_xor_sync(0xffffffffu, s, o);
    const float attn = p / s;

    const __half* yb = g_yh + nodebase * F;
    float acc0[4], acc1[4];
    #pragma unroll
    for (int j = 0; j < 4; j++) { acc0[j] = 0.f; acc1[j] = 0.f; }

    #pragma unroll
    for (int d = 0; d < D; d++) {
        const int   id0 = __shfl_sync(0xffffffffu, idx,  d);
        const float w0  = __shfl_sync(0xffffffffu, attn, d);
        const int   id1 = __shfl_sync(0xffffffffu, idx,  16 + d);
        const float w1  = __shfl_sync(0xffffffffu, attn, 16 + d);
        uint2 r0 = *(const uint2*)(yb + (size_t)id0 * F + lane * 4);
        uint2 r1 = *(const uint2*)(yb + (size_t)id1 * F + lane * 4);
        const __half2* h0 = reinterpret_cast<const __half2*>(&r0);
        const __half2* h1 = reinterpret_cast<const __half2*>(&r1);
        #pragma unroll
        for (int j = 0; j < 2; j++) {
            float2 f0 = __half22float2(h0[j]);
            float2 f1 = __half22float2(h1[j]);
            acc0[2 * j]     += w0 * f0.x;
            acc0[2 * j + 1] += w0 * f0.y;
            acc1[2 * j]     += w1 * f1.x;
            acc1[2 * j + 1] += w1 * f1.y;
        }
    }

    float4 o0, o1;
    o0.x = acc0[0]; o0.y = acc0[1]; o0.z = acc0[2]; o0.w = acc0[3];
    o1.x = acc1[0]; o1.y = acc1[1]; o1.z = acc1[2]; o1.w = acc1[3];
    o0.x = o0.x > 0.f ? o0.x : (__expf(o0.x) - 1.f);
    o0.y = o0.y > 0.f ? o0.y : (__expf(o0.y) - 1.f);
    o0.z = o0.z > 0.f ? o0.z : (__expf(o0.z) - 1.f);
    o0.w = o0.w > 0.f ? o0.w : (__expf(o0.w) - 1.f);
    o1.x = o1.x > 0.f ? o1.x : (__expf(o1.x) - 1.f);
    o1.y = o1.y > 0.f ? o1.y : (__expf(o1.y) - 1.f);
    o1.z = o1.z > 0.f ? o1.z : (__expf(o1.z) - 1.f);
    o1.w = o1.w > 0.f ? o1.w : (__expf(o1.w) - 1.f);

    *(float4*)(out + (size_t)(wg * 2)     * F + lane * 4) = o0;
    *(float4*)(out + (size_t)(wg * 2 + 1) * F + lane * 4) = o1;
}

// ---------------------------------------------------------------------------
extern "C" void kernel_launch(void* const* d_in, const int* in_sizes, int n_in,
                              void* d_out, int out_size)
{
    //   x: 10,240,000 f32 | adj: 1,280,000 (i32 or i64) | W: 16,384 f32 | a: 256 f32
    const float* x   = nullptr;
    const int*   adj = nullptr;
    const float* W   = nullptr;
    const float* a   = nullptr;
    for (int i = 0; i < n_in; i++) {
        switch (in_sizes[i]) {
            case NROWS * F: x   = (const float*)d_in[i]; break;
            case NROWS * D: adj = (const int*)d_in[i];   break;
            case F * F:     W   = (const float*)d_in[i]; break;
            case 2 * F:     a   = (const float*)d_in[i]; break;
            default: break;
        }
    }
    float* out = (float*)d_out;

    gemm_scores_kernel<<<NROWS / 64, 256>>>(x, W, a);
    attn_out_kernel<<<(NROWS / 2 * 32) / 256, 256>>>(adj, out);
}